// round 8
// baseline (speedup 1.0000x reference)
#include <cuda_runtime.h>
#include <cuda_fp16.h>

// out[b, o] = max_i min(x[b, i], W[i, o])   (fuzzy max-min composition)
// x: [1024, 512] f32, W: [512, 512] f32, out: [1024, 512] f32.
//
// R8: dense fp16 HMNMX2. Same 32m x 16n tile / 1024 CTAs (1% wave tax),
// but 2 warps per CTA SPLITTING THE K-RANGE of each stage -> 13.8 warps/SM
// (R7 had ~5-7; issue/alu were starved at 46%/51%). Warps share smem tiles,
// split the cp.async work, and max-merge partial accumulators at the end.

#define B_DIM 1024
#define IN_F  512
#define OUT_F 512

// scratch: x duplicated-half2, transposed [k][m]  (2 MB)
__device__ __align__(16) unsigned g_xd[IN_F * B_DIM];
// scratch: w packed-half2 [k][n/2]  (512 KB)
__device__ __align__(16) unsigned g_wh[IN_F * OUT_F / 2];

// ================= merged prepass =================
#define PREP_THREADS 256
#define XT_STRIDE 68

__global__ __launch_bounds__(PREP_THREADS)
void prep_kernel(const float* __restrict__ x, const float* __restrict__ w)
{
    const int t = threadIdx.x;

    if (blockIdx.x < 128) {
        // ---- x: [m][k] f32 -> [k][m] dup-half2, 64x64 tiles ----
        __shared__ unsigned t64[64][XT_STRIDE];
        const int bk = (blockIdx.x & 7) * 64;
        const int bm = (blockIdx.x >> 3) * 64;
#pragma unroll
        for (int it = 0; it < 4; it++) {
            int v = t + it * PREP_THREADS;       // 0..1023
            int r = v >> 4;                      // m row 0..63
            int c = v & 15;                      // k float4-chunk
            float4 f = *(const float4*)(x + (bm + r) * IN_F + bk + c * 4);
            __half2 h0 = __float2half2_rn(f.x);
            __half2 h1 = __float2half2_rn(f.y);
            __half2 h2 = __float2half2_rn(f.z);
            __half2 h3 = __float2half2_rn(f.w);
            t64[c * 4 + 0][r] = *(unsigned*)&h0;
            t64[c * 4 + 1][r] = *(unsigned*)&h1;
            t64[c * 4 + 2][r] = *(unsigned*)&h2;
            t64[c * 4 + 3][r] = *(unsigned*)&h3;
        }
        __syncthreads();
#pragma unroll
        for (int it = 0; it < 4; it++) {
            int v = t + it * PREP_THREADS;
            int kr = v >> 4;
            int mc = (v & 15) * 4;
            uint4 u = *(const uint4*)&t64[kr][mc];
            *(uint4*)&g_xd[(bk + kr) * B_DIM + bm + mc] = u;
        }
    } else {
        // ---- w: f32 pairs -> packed half2 ----
        const int wid = blockIdx.x - 128;
        const int f4base = wid * 512 + t * 2;
        float4 a = ((const float4*)w)[f4base];
        float4 b = ((const float4*)w)[f4base + 1];
        __half2 h0 = __floats2half2_rn(a.x, a.y);
        __half2 h1 = __floats2half2_rn(a.z, a.w);
        __half2 h2 = __floats2half2_rn(b.x, b.y);
        __half2 h3 = __floats2half2_rn(b.z, b.w);
        ((uint4*)g_wh)[wid * 256 + t] = make_uint4(
            *(unsigned*)&h0, *(unsigned*)&h1, *(unsigned*)&h2, *(unsigned*)&h3);
    }
}

// ================= main kernel: 2-warp CTAs, split-k =================
#define BM 32
#define BN 16
#define BK 64
#define NKT (IN_F / BK)   // 8
#define THREADS 64

__device__ __forceinline__ void issue_stage(int t, int bm, int bn_h, int kt,
                                            unsigned (*xs)[BM], unsigned (*ws)[BN / 2])
{
#pragma unroll
    for (int it = 0; it < 8; it++) {            // 64x32 uints = 512 uint4
        int v = t + it * THREADS;               // 0..511
        int r = v >> 3;                         // k row 0..63
        int c = (v & 7) * 4;
        unsigned dst = (unsigned)__cvta_generic_to_shared(&xs[r][c]);
        const unsigned* src = &g_xd[(kt + r) * B_DIM + bm + c];
        asm volatile("cp.async.cg.shared.global [%0], [%1], 16;\n" :: "r"(dst), "l"(src));
    }
#pragma unroll
    for (int it = 0; it < 2; it++) {            // 64x8 uints = 128 uint4
        int v = t + it * THREADS;               // 0..127
        int r = v >> 1;                         // k row 0..63
        int c = (v & 1) * 4;
        unsigned dst = (unsigned)__cvta_generic_to_shared(&ws[r][c]);
        const unsigned* src = &g_wh[(kt + r) * (OUT_F / 2) + bn_h + c];
        asm volatile("cp.async.cg.shared.global [%0], [%1], 16;\n" :: "r"(dst), "l"(src));
    }
    asm volatile("cp.async.commit_group;\n");
}

__global__ __launch_bounds__(THREADS, 8)
void maxmin_main(float* __restrict__ out)
{
    __shared__ unsigned xs[2][BK][BM];        // dup half2, 16 KB
    __shared__ unsigned ws[2][BK][BN / 2];    // packed half2, 4 KB
    __shared__ unsigned merge[32 * 8];        // warp-1 partials, 1 KB

    const int t    = threadIdx.x;             // 0..63
    const int warp = t >> 5;                  // 0,1: k-range owner
    const int lane = t & 31;
    const int bn   = blockIdx.x * BN;          // 32 n-blocks
    const int bm   = blockIdx.y * BM;          // 32 m-blocks
    const int bn_h = bn / 2;
    const int koff = warp * 32;                // this warp's k offset in a stage

    const int tm4 = (lane >> 2) * 4;   // m rows tm4..tm4+3
    const int tn2 = (lane & 3) * 2;    // half2 cols tn2, tn2+1

    issue_stage(t, bm, bn_h, 0, xs[0], ws[0]);
    issue_stage(t, bm, bn_h, BK, xs[1], ws[1]);

    __half2 acc[4][2];                 // inputs >= 0: 0 is max-identity
#pragma unroll
    for (int i = 0; i < 4; i++) {
        acc[i][0] = __float2half2_rn(0.f);
        acc[i][1] = __float2half2_rn(0.f);
    }

    for (int i = 0; i < NKT; i++) {
        if (i + 1 < NKT) asm volatile("cp.async.wait_group 1;\n");
        else             asm volatile("cp.async.wait_group 0;\n");
        __syncthreads();

        const int s = i & 1;
#pragma unroll 8
        for (int kk = 0; kk < 32; kk++) {           // this warp's half of BK
            const int k = koff + kk;
            uint4 xv = *(const uint4*)&xs[s][k][tm4];
            __half2 x0 = *(__half2*)&xv.x, x1 = *(__half2*)&xv.y;
            __half2 x2 = *(__half2*)&xv.z, x3 = *(__half2*)&xv.w;
            __half2 w0 = *(const __half2*)&ws[s][k][tn2];
            __half2 w1 = *(const __half2*)&ws[s][k][tn2 + 1];
            acc[0][0] = __hmax2(acc[0][0], __hmin2(x0, w0));
            acc[0][1] = __hmax2(acc[0][1], __hmin2(x0, w1));
            acc[1][0] = __hmax2(acc[1][0], __hmin2(x1, w0));
            acc[1][1] = __hmax2(acc[1][1], __hmin2(x1, w1));
            acc[2][0] = __hmax2(acc[2][0], __hmin2(x2, w0));
            acc[2][1] = __hmax2(acc[2][1], __hmin2(x2, w1));
            acc[3][0] = __hmax2(acc[3][0], __hmin2(x3, w0));
            acc[3][1] = __hmax2(acc[3][1], __hmin2(x3, w1));
        }
        __syncthreads();

        if (i + 2 < NKT)
            issue_stage(t, bm, bn_h, (i + 2) * BK, xs[s], ws[s]);
    }

    // ---- merge warp 1's partials into warp 0, then store ----
    if (warp == 1) {
        unsigned* mb = &merge[lane * 8];
#pragma unroll
        for (int i = 0; i < 4; i++) {
            mb[i * 2 + 0] = *(unsigned*)&acc[i][0];
            mb[i * 2 + 1] = *(unsigned*)&acc[i][1];
        }
    }
    __syncthreads();
    if (warp == 0) {
        const unsigned* mb = &merge[lane * 8];
#pragma unroll
        for (int i = 0; i < 4; i++) {
            acc[i][0] = __hmax2(acc[i][0], *(const __half2*)&mb[i * 2 + 0]);
            acc[i][1] = __hmax2(acc[i][1], *(const __half2*)&mb[i * 2 + 1]);
            float2 a = __half22float2(acc[i][0]);
            float2 b = __half22float2(acc[i][1]);
            *(float4*)(out + (bm + tm4 + i) * OUT_F + bn + tn2 * 2) =
                make_float4(a.x, a.y, b.x, b.y);
        }
    }
}

extern "C" void kernel_launch(void* const* d_in, const int* in_sizes, int n_in,
                              void* d_out, int out_size)
{
    const float* x = (const float*)d_in[0];   // [1024, 512]
    const float* w = (const float*)d_in[1];   // [512, 512]
    float* out = (float*)d_out;               // [1024, 512]

    prep_kernel<<<256, PREP_THREADS>>>(x, w);

    dim3 grid(OUT_F / BN, B_DIM / BM);        // (32, 32) = 1024 CTAs
    maxmin_main<<<grid, THREADS>>>(out);
}